// round 5
// baseline (speedup 1.0000x reference)
#include <cuda_runtime.h>
#include <math.h>

#define ROWS 131072
#define KCODES 1024
#define DIM 32
#define RPT 4
#define THREADS 256
#define NBLOCKS (ROWS / (THREADS * RPT))   // 128
#define TAU 5e-4f      // coarse trigger (>> my fp32 score noise)
#define EPS 5e-5f      // reference tie window: ~6 ulps at s1+s2 magnitude ~64

// output layout (fp32 concatenation of the 7-tuple)
#define OFF_LOSS  0
#define OFF_QUANT 1
#define OFF_PERP  (OFF_QUANT + ROWS * DIM)
#define OFF_IDX   (OFF_PERP + 1)
#define OFF_EMB   (OFF_IDX + ROWS)
#define OFF_CS    (OFF_EMB + KCODES * DIM)
#define OFF_EMAW  (OFF_CS + KCODES)

__device__ float g_counts[KCODES];
__device__ float g_dw[KCODES * DIM];
__device__ float g_loss;

__global__ void k_zero() {
    int t = blockIdx.x * blockDim.x + threadIdx.x;
    if (t < KCODES * DIM) g_dw[t] = 0.0f;
    if (t < KCODES)       g_counts[t] = 0.0f;
    if (t == 0)           g_loss = 0.0f;
}

__device__ __forceinline__ void two_sum(float a, float b, float &s, float &e) {
    s = a + b;
    float bb = s - a;
    e = (a - (s - bb)) + (b - bb);
}

// exact-ish score  ||e_j||^2 - 2 x.e_j  in float-float
__device__ __forceinline__ void score_ff(const float* __restrict__ x,
                                         const float* __restrict__ se,
                                         float sch, float scl, int j,
                                         float &rh, float &rl)
{
    float dh = 0.0f, dl = 0.0f;
    #pragma unroll
    for (int k = 0; k < DIM; k++) {
        float xv = x[k];
        float ev = se[j * DIM + k];
        float p  = xv * ev;
        float pe = fmaf(xv, ev, -p);
        float s, err; two_sum(dh, p, s, err);
        dh = s; dl += (err + pe);
    }
    float h2 = -2.0f * dh, l2 = -2.0f * dl;   // exact scaling
    float sh, serr; two_sum(sch, h2, sh, serr);
    float sl = serr + scl + l2;
    two_sum(sh, sl, rh, rl);
}

// ---------------------------------------------------------------------------
// main: fast fp32 argmin; contested rows get exact rescan + lowest-index
// tie-break within the reference's fp32 cancellation-noise window.
// shared: codebook 128KB + ||e||^2 hi 4KB + lo 4KB = 136KB
// ---------------------------------------------------------------------------
extern __shared__ float smem[];

__global__ void __launch_bounds__(THREADS) k_main(
    const float* __restrict__ flat,
    const float* __restrict__ emb,
    float* __restrict__ out)
{
    float* se  = smem;                       // [KCODES*DIM]
    float* sch = smem + KCODES * DIM;        // [KCODES] ||e||^2 hi
    float* scl = sch + KCODES;               // [KCODES] ||e||^2 lo
    const int tid = threadIdx.x;

    {
        const float4* e4 = (const float4*)emb;
        float4* s4 = (float4*)se;
        #pragma unroll 4
        for (int i = tid; i < KCODES * DIM / 4; i += THREADS) s4[i] = e4[i];
    }
    __syncthreads();

    for (int j = tid; j < KCODES; j += THREADS) {
        float dh = 0.0f, dl = 0.0f;
        #pragma unroll
        for (int k = 0; k < DIM; k++) {
            float v = se[j * DIM + k];
            float p = v * v;
            float pe = fmaf(v, v, -p);
            float s, err; two_sum(dh, p, s, err);
            dh = s; dl += (err + pe);
        }
        float h, l; two_sum(dh, dl, h, l);
        sch[j] = h; scl[j] = l;
    }
    __syncthreads();

    const int g  = blockIdx.x * THREADS + tid;
    const int r0 = g * RPT;

    float x[RPT][DIM];
    #pragma unroll
    for (int rr = 0; rr < RPT; rr++) {
        const float4* xr = (const float4*)(flat + (size_t)(r0 + rr) * DIM);
        #pragma unroll
        for (int q = 0; q < DIM / 4; q++) {
            float4 v = xr[q];
            x[rr][4*q+0] = v.x; x[rr][4*q+1] = v.y;
            x[rr][4*q+2] = v.z; x[rr][4*q+3] = v.w;
        }
    }

    float best[RPT], best2[RPT];
    int   bi[RPT];
    #pragma unroll
    for (int rr = 0; rr < RPT; rr++) { best[rr] = 3.4e38f; best2[rr] = 3.4e38f; bi[rr] = 0; }

    const float4* se4 = (const float4*)se;
    for (int j = 0; j < KCODES; j++) {
        float a0[RPT], a1[RPT], a2[RPT], a3[RPT];
        #pragma unroll
        for (int rr = 0; rr < RPT; rr++) { a0[rr]=0; a1[rr]=0; a2[rr]=0; a3[rr]=0; }
        #pragma unroll
        for (int q = 0; q < 2; q++) {
            float4 e0 = se4[j*8 + q];
            float4 e1 = se4[j*8 + 2 + q];
            float4 e2 = se4[j*8 + 4 + q];
            float4 e3 = se4[j*8 + 6 + q];
            #pragma unroll
            for (int rr = 0; rr < RPT; rr++) {
                a0[rr] = fmaf(x[rr][4*q+0],   e0.x, a0[rr]);
                a0[rr] = fmaf(x[rr][4*q+1],   e0.y, a0[rr]);
                a0[rr] = fmaf(x[rr][4*q+2],   e0.z, a0[rr]);
                a0[rr] = fmaf(x[rr][4*q+3],   e0.w, a0[rr]);
                a1[rr] = fmaf(x[rr][8+4*q+0], e1.x, a1[rr]);
                a1[rr] = fmaf(x[rr][8+4*q+1], e1.y, a1[rr]);
                a1[rr] = fmaf(x[rr][8+4*q+2], e1.z, a1[rr]);
                a1[rr] = fmaf(x[rr][8+4*q+3], e1.w, a1[rr]);
                a2[rr] = fmaf(x[rr][16+4*q+0], e2.x, a2[rr]);
                a2[rr] = fmaf(x[rr][16+4*q+1], e2.y, a2[rr]);
                a2[rr] = fmaf(x[rr][16+4*q+2], e2.z, a2[rr]);
                a2[rr] = fmaf(x[rr][16+4*q+3], e2.w, a2[rr]);
                a3[rr] = fmaf(x[rr][24+4*q+0], e3.x, a3[rr]);
                a3[rr] = fmaf(x[rr][24+4*q+1], e3.y, a3[rr]);
                a3[rr] = fmaf(x[rr][24+4*q+2], e3.z, a3[rr]);
                a3[rr] = fmaf(x[rr][24+4*q+3], e3.w, a3[rr]);
            }
        }
        float cj = sch[j];
        #pragma unroll
        for (int rr = 0; rr < RPT; rr++) {
            float dot = (a0[rr] + a1[rr]) + (a2[rr] + a3[rr]);
            float s = fmaf(-2.0f, dot, cj);
            if (s < best[rr])       { best2[rr] = best[rr]; best[rr] = s; bi[rr] = j; }
            else if (s < best2[rr]) { best2[rr] = s; }
        }
    }

    // contested rows: exact rescan; then LOWEST index within EPS of exact best
    // (mimics jnp.argmin's first-min behavior on reference fp32 near-ties)
    #pragma unroll
    for (int rr = 0; rr < RPT; rr++) {
        if (best2[rr] - best[rr] < TAU) {
            // pass 1: exact best value
            float bh = 3.4e38f, bl = 0.0f;
            for (int j = 0; j < KCODES; j++) {
                float rh, rl;
                score_ff(x[rr], se, sch[j], scl[j], j, rh, rl);
                if (rh < bh || (rh == bh && rl < bl)) { bh = rh; bl = rl; }
            }
            // pass 2: lowest index within EPS of exact best
            int pick = KCODES;
            for (int j = 0; j < KCODES; j++) {
                float rh, rl;
                score_ff(x[rr], se, sch[j], scl[j], j, rh, rl);
                float diff = (rh - bh) + (rl - bl);
                if (diff < EPS) { pick = j; break; }
            }
            bi[rr] = (pick < KCODES) ? pick : bi[rr];
        }
    }

    // epilogue: outputs + stats
    float lsum = 0.0f;
    #pragma unroll
    for (int rr = 0; rr < RPT; rr++) {
        const int row = r0 + rr;
        const int j = bi[rr];
        out[OFF_IDX + row] = (float)j;
        atomicAdd(&g_counts[j], 1.0f);
        float* qout = out + OFF_QUANT + (size_t)row * DIM;
        #pragma unroll
        for (int k = 0; k < DIM; k++) {
            float qv = se[j * DIM + k];
            qout[k] = qv;
            float d = qv - x[rr][k];
            lsum = fmaf(d, d, lsum);
            atomicAdd(&g_dw[j * DIM + k], x[rr][k]);
        }
    }

    __shared__ float red[THREADS / 32];
    #pragma unroll
    for (int off = 16; off > 0; off >>= 1)
        lsum += __shfl_down_sync(0xFFFFFFFFu, lsum, off);
    if ((tid & 31) == 0) red[tid >> 5] = lsum;
    __syncthreads();
    if (tid == 0) {
        float s = 0.0f;
        #pragma unroll
        for (int w = 0; w < THREADS / 32; w++) s += red[w];
        atomicAdd(&g_loss, s);
    }
}

// ---------------------------------------------------------------------------
__global__ void k_fin(const float* __restrict__ cs_in,
                      const float* __restrict__ ema_w,
                      float* __restrict__ out)
{
    __shared__ float sh[KCODES];
    __shared__ float n_sh;
    const int t = threadIdx.x;

    float cnt = g_counts[t];
    float pre = cs_in[t] * 0.99f + 0.01f * cnt;

    sh[t] = pre;
    __syncthreads();
    for (int s = KCODES / 2; s > 0; s >>= 1) {
        if (t < s) sh[t] += sh[t + s];
        __syncthreads();
    }
    if (t == 0) n_sh = sh[0];
    __syncthreads();
    const float n = n_sh;

    const float ncs = (pre + 1e-5f) / (n + (float)KCODES * 1e-5f) * n;
    out[OFF_CS + t] = ncs;

    float p = cnt / (float)ROWS;
    float h = -p * logf(p + 1e-10f);
    __syncthreads();
    sh[t] = h;
    __syncthreads();
    for (int s = KCODES / 2; s > 0; s >>= 1) {
        if (t < s) sh[t] += sh[t + s];
        __syncthreads();
    }
    if (t == 0) {
        out[OFF_PERP] = expf(sh[0]);
        out[OFF_LOSS] = 0.25f * g_loss / (float)(ROWS * DIM);
    }

    #pragma unroll
    for (int k = 0; k < DIM; k++) {
        int i = t * DIM + k;
        float w = ema_w[i] * 0.99f + 0.01f * g_dw[i];
        out[OFF_EMAW + i] = w;
        out[OFF_EMB  + i] = w / ncs;
    }
}

// ---------------------------------------------------------------------------
extern "C" void kernel_launch(void* const* d_in, const int* in_sizes, int n_in,
                              void* d_out, int out_size)
{
    const float* inputs = (const float*)d_in[0];
    const float* emb    = (const float*)d_in[1];
    const float* cs     = (const float*)d_in[2];
    const float* emaw   = (const float*)d_in[3];
    float* out = (float*)d_out;

    size_t smem = (size_t)(KCODES * DIM + 2 * KCODES) * sizeof(float);  // 136 KB
    cudaFuncSetAttribute(k_main, cudaFuncAttributeMaxDynamicSharedMemorySize, (int)smem);

    k_zero<<<(KCODES * DIM + 1023) / 1024, 1024>>>();
    k_main<<<NBLOCKS, THREADS, smem>>>(inputs, emb, out);
    k_fin<<<1, KCODES>>>(cs, emaw, out);
}

// round 7
// speedup vs baseline: 1.4206x; 1.4206x over previous
#include <cuda_runtime.h>
#include <math.h>

#define ROWS 131072
#define KCODES 1024
#define DIM 32
#define RPT 4
#define THREADS 256
#define NBLOCKS (ROWS / (THREADS * RPT))   // 128
#define TAU 5e-4f      // contested-row trigger (>> fp32 score noise)
#define EPS 5e-5f      // reference tie window (~6 ulps at magnitude ~64)
#define MAXWORK 4096

// output layout (fp32 concatenation of the 7-tuple)
#define OFF_LOSS  0
#define OFF_QUANT 1
#define OFF_PERP  (OFF_QUANT + ROWS * DIM)
#define OFF_IDX   (OFF_PERP + 1)
#define OFF_EMB   (OFF_IDX + ROWS)
#define OFF_CS    (OFF_EMB + KCODES * DIM)
#define OFF_EMAW  (OFF_CS + KCODES)

__device__ float g_counts[KCODES];
__device__ float g_dw[KCODES * DIM];
__device__ float g_loss;
__device__ int   g_nwork;
__device__ int   g_work[MAXWORK];

__global__ void k_zero() {
    int t = blockIdx.x * blockDim.x + threadIdx.x;
    if (t < KCODES * DIM) g_dw[t] = 0.0f;
    if (t < KCODES)       g_counts[t] = 0.0f;
    if (t == 0)         { g_loss = 0.0f; g_nwork = 0; }
}

__device__ __forceinline__ void two_sum(float a, float b, float &s, float &e) {
    s = a + b;
    float bb = s - a;
    e = (a - (s - bb)) + (b - bb);
}

// ---------------------------------------------------------------------------
// k_main: pure fp32 fast path. x stays in registers (constant indexing only;
// NO pointers taken into it). Contested rows go to the worklist.
// shared: codebook 128KB + ||e||^2 4KB = 132KB
// ---------------------------------------------------------------------------
extern __shared__ float smem[];

__global__ void __launch_bounds__(THREADS) k_main(
    const float* __restrict__ flat,
    const float* __restrict__ emb,
    float* __restrict__ out)
{
    float* se = smem;                 // [KCODES*DIM]
    float* sc = smem + KCODES * DIM;  // [KCODES]
    const int tid = threadIdx.x;

    {
        const float4* e4 = (const float4*)emb;
        float4* s4 = (float4*)se;
        #pragma unroll 4
        for (int i = tid; i < KCODES * DIM / 4; i += THREADS) s4[i] = e4[i];
    }
    __syncthreads();
    for (int j = tid; j < KCODES; j += THREADS) {
        float s = 0.0f;
        #pragma unroll
        for (int k = 0; k < DIM; k++) s = fmaf(se[j*DIM+k], se[j*DIM+k], s);
        sc[j] = s;
    }
    __syncthreads();

    const int g  = blockIdx.x * THREADS + tid;
    const int r0 = g * RPT;

    float x[RPT][DIM];
    #pragma unroll
    for (int rr = 0; rr < RPT; rr++) {
        const float4* xr = (const float4*)(flat + (size_t)(r0 + rr) * DIM);
        #pragma unroll
        for (int q = 0; q < DIM / 4; q++) {
            float4 v = xr[q];
            x[rr][4*q+0] = v.x; x[rr][4*q+1] = v.y;
            x[rr][4*q+2] = v.z; x[rr][4*q+3] = v.w;
        }
    }

    float best[RPT], best2[RPT];
    int   bi[RPT];
    #pragma unroll
    for (int rr = 0; rr < RPT; rr++) { best[rr] = 3.4e38f; best2[rr] = 3.4e38f; bi[rr] = 0; }

    const float4* se4 = (const float4*)se;
    for (int j = 0; j < KCODES; j++) {
        float a0[RPT], a1[RPT], a2[RPT], a3[RPT];
        #pragma unroll
        for (int rr = 0; rr < RPT; rr++) { a0[rr]=0; a1[rr]=0; a2[rr]=0; a3[rr]=0; }
        #pragma unroll
        for (int q = 0; q < 2; q++) {
            float4 e0 = se4[j*8 + q];
            float4 e1 = se4[j*8 + 2 + q];
            float4 e2 = se4[j*8 + 4 + q];
            float4 e3 = se4[j*8 + 6 + q];
            #pragma unroll
            for (int rr = 0; rr < RPT; rr++) {
                a0[rr] = fmaf(x[rr][4*q+0],   e0.x, a0[rr]);
                a0[rr] = fmaf(x[rr][4*q+1],   e0.y, a0[rr]);
                a0[rr] = fmaf(x[rr][4*q+2],   e0.z, a0[rr]);
                a0[rr] = fmaf(x[rr][4*q+3],   e0.w, a0[rr]);
                a1[rr] = fmaf(x[rr][8+4*q+0], e1.x, a1[rr]);
                a1[rr] = fmaf(x[rr][8+4*q+1], e1.y, a1[rr]);
                a1[rr] = fmaf(x[rr][8+4*q+2], e1.z, a1[rr]);
                a1[rr] = fmaf(x[rr][8+4*q+3], e1.w, a1[rr]);
                a2[rr] = fmaf(x[rr][16+4*q+0], e2.x, a2[rr]);
                a2[rr] = fmaf(x[rr][16+4*q+1], e2.y, a2[rr]);
                a2[rr] = fmaf(x[rr][16+4*q+2], e2.z, a2[rr]);
                a2[rr] = fmaf(x[rr][16+4*q+3], e2.w, a2[rr]);
                a3[rr] = fmaf(x[rr][24+4*q+0], e3.x, a3[rr]);
                a3[rr] = fmaf(x[rr][24+4*q+1], e3.y, a3[rr]);
                a3[rr] = fmaf(x[rr][24+4*q+2], e3.z, a3[rr]);
                a3[rr] = fmaf(x[rr][24+4*q+3], e3.w, a3[rr]);
            }
        }
        float cj = sc[j];
        #pragma unroll
        for (int rr = 0; rr < RPT; rr++) {
            float dot = (a0[rr] + a1[rr]) + (a2[rr] + a3[rr]);
            float s = fmaf(-2.0f, dot, cj);
            if (s < best[rr])       { best2[rr] = best[rr]; best[rr] = s; bi[rr] = j; }
            else if (s < best2[rr]) { best2[rr] = s; }
        }
    }

    // epilogue: non-contested rows only; contested rows -> worklist
    float lsum = 0.0f;
    #pragma unroll
    for (int rr = 0; rr < RPT; rr++) {
        const int row = r0 + rr;
        bool contested = (best2[rr] - best[rr] < TAU);
        if (contested) {
            int slot = atomicAdd(&g_nwork, 1);
            if (slot < MAXWORK) { g_work[slot] = row; continue; }
            // overflow fallback (should never happen): treat as normal
        }
        const int j = bi[rr];
        out[OFF_IDX + row] = (float)j;
        atomicAdd(&g_counts[j], 1.0f);
        float* qout = out + OFF_QUANT + (size_t)row * DIM;
        #pragma unroll
        for (int k = 0; k < DIM; k++) {
            float qv = se[j * DIM + k];
            qout[k] = qv;
            float d = qv - x[rr][k];
            lsum = fmaf(d, d, lsum);
            atomicAdd(&g_dw[j * DIM + k], x[rr][k]);
        }
    }

    __shared__ float red[THREADS / 32];
    #pragma unroll
    for (int off = 16; off > 0; off >>= 1)
        lsum += __shfl_down_sync(0xFFFFFFFFu, lsum, off);
    if ((tid & 31) == 0) red[tid >> 5] = lsum;
    __syncthreads();
    if (tid == 0) {
        float s = 0.0f;
        #pragma unroll
        for (int w = 0; w < THREADS / 32; w++) s += red[w];
        atomicAdd(&g_loss, s);
    }
}

// ---------------------------------------------------------------------------
// k_refine: handles contested rows exactly as the passing R5 logic:
// exact ff rescan, then LOWEST index within EPS of exact best.
// One warp per contested row. 1 block.
// shared: codebook 128KB + norms hi/lo 8KB + xbuf 1KB
// ---------------------------------------------------------------------------
__global__ void __launch_bounds__(256) k_refine(
    const float* __restrict__ flat,
    const float* __restrict__ emb,
    float* __restrict__ out)
{
    extern __shared__ float rsm[];
    float* se  = rsm;                        // [KCODES*DIM]
    float* sch = rsm + KCODES * DIM;         // [KCODES]
    float* scl = sch + KCODES;               // [KCODES]
    float* xbuf = scl + KCODES;              // [8][DIM]
    const int tid  = threadIdx.x;
    const int wid  = tid / 32;
    const int lane = tid % 32;

    {
        const float4* e4 = (const float4*)emb;
        float4* s4 = (float4*)se;
        for (int i = tid; i < KCODES * DIM / 4; i += 256) s4[i] = e4[i];
    }
    __syncthreads();
    for (int j = tid; j < KCODES; j += 256) {
        float dh = 0.0f, dl = 0.0f;
        #pragma unroll
        for (int k = 0; k < DIM; k++) {
            float v = se[j * DIM + k];
            float p = v * v;
            float pe = fmaf(v, v, -p);
            float s, err; two_sum(dh, p, s, err);
            dh = s; dl += (err + pe);
        }
        float h, l; two_sum(dh, dl, h, l);
        sch[j] = h; scl[j] = l;
    }
    __syncthreads();

    int nw = g_nwork; if (nw > MAXWORK) nw = MAXWORK;

    for (int w = wid; w < nw; w += 8) {
        const int row = g_work[w];
        // stage x into shared (dynamic indexing OK here; cold path)
        float xk = flat[(size_t)row * DIM + lane];
        xbuf[wid * DIM + lane] = xk;
        __syncwarp();
        const float* xp = &xbuf[wid * DIM];

        // phase 1: exact ff best over all codes (each lane: 32 codes)
        float bh = 3.4e38f, bl = 0.0f;
        for (int j = lane; j < KCODES; j += 32) {
            float dh = 0.0f, dl = 0.0f;
            for (int k = 0; k < DIM; k++) {
                float xv = xp[k];
                float ev = se[j * DIM + k];
                float p  = xv * ev;
                float pe = fmaf(xv, ev, -p);
                float s, err; two_sum(dh, p, s, err);
                dh = s; dl += (err + pe);
            }
            float h2 = -2.0f * dh, l2 = -2.0f * dl;
            float sh, serr; two_sum(sch[j], h2, sh, serr);
            float sl = serr + scl[j] + l2;
            float rh, rl; two_sum(sh, sl, rh, rl);
            if (rh < bh || (rh == bh && rl < bl)) { bh = rh; bl = rl; }
        }
        #pragma unroll
        for (int off = 16; off > 0; off >>= 1) {
            float oh = __shfl_xor_sync(0xFFFFFFFFu, bh, off);
            float ol = __shfl_xor_sync(0xFFFFFFFFu, bl, off);
            if (oh < bh || (oh == bh && ol < bl)) { bh = oh; bl = ol; }
        }

        // phase 2: lowest index within EPS of exact best
        int pick = KCODES;
        for (int j = lane; j < KCODES; j += 32) {
            float dh = 0.0f, dl = 0.0f;
            for (int k = 0; k < DIM; k++) {
                float xv = xp[k];
                float ev = se[j * DIM + k];
                float p  = xv * ev;
                float pe = fmaf(xv, ev, -p);
                float s, err; two_sum(dh, p, s, err);
                dh = s; dl += (err + pe);
            }
            float h2 = -2.0f * dh, l2 = -2.0f * dl;
            float sh, serr; two_sum(sch[j], h2, sh, serr);
            float sl = serr + scl[j] + l2;
            float rh, rl; two_sum(sh, sl, rh, rl);
            float diff = (rh - bh) + (rl - bl);
            if (diff < EPS) { pick = j; break; }
        }
        #pragma unroll
        for (int off = 16; off > 0; off >>= 1) {
            int op = __shfl_xor_sync(0xFFFFFFFFu, pick, off);
            pick = min(pick, op);
        }

        // write results + stats (lane k handles element k)
        const int j = pick;
        float qv = se[j * DIM + lane];
        out[OFF_QUANT + (size_t)row * DIM + lane] = qv;
        atomicAdd(&g_dw[j * DIM + lane], xk);
        float d = qv - xk;
        float l2s = d * d;
        #pragma unroll
        for (int off = 16; off > 0; off >>= 1)
            l2s += __shfl_down_sync(0xFFFFFFFFu, l2s, off);
        if (lane == 0) {
            out[OFF_IDX + row] = (float)j;
            atomicAdd(&g_counts[j], 1.0f);
            atomicAdd(&g_loss, l2s);
        }
        __syncwarp();
    }
}

// ---------------------------------------------------------------------------
__global__ void k_fin(const float* __restrict__ cs_in,
                      const float* __restrict__ ema_w,
                      float* __restrict__ out)
{
    __shared__ float sh[KCODES];
    __shared__ float n_sh;
    const int t = threadIdx.x;

    float cnt = g_counts[t];
    float pre = cs_in[t] * 0.99f + 0.01f * cnt;

    sh[t] = pre;
    __syncthreads();
    for (int s = KCODES / 2; s > 0; s >>= 1) {
        if (t < s) sh[t] += sh[t + s];
        __syncthreads();
    }
    if (t == 0) n_sh = sh[0];
    __syncthreads();
    const float n = n_sh;

    const float ncs = (pre + 1e-5f) / (n + (float)KCODES * 1e-5f) * n;
    out[OFF_CS + t] = ncs;

    float p = cnt / (float)ROWS;
    float h = -p * logf(p + 1e-10f);
    __syncthreads();
    sh[t] = h;
    __syncthreads();
    for (int s = KCODES / 2; s > 0; s >>= 1) {
        if (t < s) sh[t] += sh[t + s];
        __syncthreads();
    }
    if (t == 0) {
        out[OFF_PERP] = expf(sh[0]);
        out[OFF_LOSS] = 0.25f * g_loss / (float)(ROWS * DIM);
    }

    #pragma unroll
    for (int k = 0; k < DIM; k++) {
        int i = t * DIM + k;
        float w = ema_w[i] * 0.99f + 0.01f * g_dw[i];
        out[OFF_EMAW + i] = w;
        out[OFF_EMB  + i] = w / ncs;
    }
}

// ---------------------------------------------------------------------------
extern "C" void kernel_launch(void* const* d_in, const int* in_sizes, int n_in,
                              void* d_out, int out_size)
{
    const float* inputs = (const float*)d_in[0];
    const float* emb    = (const float*)d_in[1];
    const float* cs     = (const float*)d_in[2];
    const float* emaw   = (const float*)d_in[3];
    float* out = (float*)d_out;

    size_t smem_main = (size_t)(KCODES * DIM + KCODES) * sizeof(float);          // 132 KB
    size_t smem_ref  = (size_t)(KCODES * DIM + 2 * KCODES + 8 * DIM) * sizeof(float); // 137 KB
    cudaFuncSetAttribute(k_main,   cudaFuncAttributeMaxDynamicSharedMemorySize, (int)smem_main);
    cudaFuncSetAttribute(k_refine, cudaFuncAttributeMaxDynamicSharedMemorySize, (int)smem_ref);

    k_zero<<<(KCODES * DIM + 1023) / 1024, 1024>>>();
    k_main<<<NBLOCKS, THREADS, smem_main>>>(inputs, emb, out);
    k_refine<<<1, 256, smem_ref>>>(inputs, emb, out);
    k_fin<<<1, KCODES>>>(cs, emaw, out);
}

// round 8
// speedup vs baseline: 2.8111x; 1.9788x over previous
#include <cuda_runtime.h>
#include <math.h>

#define ROWS 131072
#define KCODES 1024
#define DIM 32
#define RPT 4
#define THREADS 256
#define NBLOCKS (ROWS / (THREADS * RPT))   // 128
#define TAU 5e-4f      // contested-row trigger (>> fp32 score noise)
#define EPS 5e-5f      // reference tie window (~6 ulps at magnitude ~64)
#define MAXWORK 4096
#define REFBLOCKS 64

// output layout (fp32 concatenation of the 7-tuple)
#define OFF_LOSS  0
#define OFF_QUANT 1
#define OFF_PERP  (OFF_QUANT + ROWS * DIM)
#define OFF_IDX   (OFF_PERP + 1)
#define OFF_EMB   (OFF_IDX + ROWS)
#define OFF_CS    (OFF_EMB + KCODES * DIM)
#define OFF_EMAW  (OFF_CS + KCODES)

__device__ float g_counts[KCODES];
__device__ float g_dw[KCODES * DIM];
__device__ float g_ncs[KCODES];
__device__ float g_loss;
__device__ int   g_nwork;
__device__ int   g_work[MAXWORK];

__global__ void k_zero() {
    int t = blockIdx.x * blockDim.x + threadIdx.x;
    if (t < KCODES * DIM) g_dw[t] = 0.0f;
    if (t < KCODES)       g_counts[t] = 0.0f;
    if (t == 0)         { g_loss = 0.0f; g_nwork = 0; }
}

// ---- packed fp32 helpers (Blackwell f32x2) --------------------------------
__device__ __forceinline__ unsigned long long ffma2(unsigned long long a,
                                                    unsigned long long b,
                                                    unsigned long long c) {
    unsigned long long d;
    asm("fma.rn.f32x2 %0, %1, %2, %3;" : "=l"(d) : "l"(a), "l"(b), "l"(c));
    return d;
}
__device__ __forceinline__ unsigned long long addf2(unsigned long long a,
                                                    unsigned long long b) {
    unsigned long long d;
    asm("add.rn.f32x2 %0, %1, %2;" : "=l"(d) : "l"(a), "l"(b));
    return d;
}
__device__ __forceinline__ float ulo(unsigned long long u) {
    return __uint_as_float((unsigned)u);
}
__device__ __forceinline__ float uhi(unsigned long long u) {
    return __uint_as_float((unsigned)(u >> 32));
}

__device__ __forceinline__ void two_sum(float a, float b, float &s, float &e) {
    s = a + b;
    float bb = s - a;
    e = (a - (s - bb)) + (b - bb);
}

// ---------------------------------------------------------------------------
// k_main: fp32 fast path with packed FFMA2. Contested rows -> worklist.
// shared: codebook 128KB + ||e||^2 4KB = 132KB
// ---------------------------------------------------------------------------
extern __shared__ float smem[];

__global__ void __launch_bounds__(THREADS) k_main(
    const float* __restrict__ flat,
    const float* __restrict__ emb,
    float* __restrict__ out)
{
    float* se = smem;                 // [KCODES*DIM]
    float* sc = smem + KCODES * DIM;  // [KCODES]
    const int tid = threadIdx.x;

    {
        const float4* e4 = (const float4*)emb;
        float4* s4 = (float4*)se;
        #pragma unroll 4
        for (int i = tid; i < KCODES * DIM / 4; i += THREADS) s4[i] = e4[i];
    }
    __syncthreads();
    for (int j = tid; j < KCODES; j += THREADS) {
        float s = 0.0f;
        #pragma unroll
        for (int k = 0; k < DIM; k++) s = fmaf(se[j*DIM+k], se[j*DIM+k], s);
        sc[j] = s;
    }
    __syncthreads();

    const int g  = blockIdx.x * THREADS + tid;
    const int r0 = g * RPT;

    // x rows as packed pairs: ux[rr][p] = (x[2p], x[2p+1])
    unsigned long long ux[RPT][DIM / 2];
    #pragma unroll
    for (int rr = 0; rr < RPT; rr++) {
        const ulonglong2* xr = (const ulonglong2*)(flat + (size_t)(r0 + rr) * DIM);
        #pragma unroll
        for (int q = 0; q < DIM / 4; q++) {
            ulonglong2 v = xr[q];
            ux[rr][2*q]   = v.x;
            ux[rr][2*q+1] = v.y;
        }
    }

    float best[RPT], best2[RPT];
    int   bi[RPT];
    #pragma unroll
    for (int rr = 0; rr < RPT; rr++) { best[rr] = 3.4e38f; best2[rr] = 3.4e38f; bi[rr] = 0; }

    const ulonglong2* se2 = (const ulonglong2*)se;
    for (int j = 0; j < KCODES; j++) {
        unsigned long long accA[RPT], accB[RPT];
        #pragma unroll
        for (int rr = 0; rr < RPT; rr++) { accA[rr] = 0ull; accB[rr] = 0ull; }

        #pragma unroll
        for (int q = 0; q < 4; q++) {            // dims 0..15
            ulonglong2 ev = se2[j*8 + q];
            #pragma unroll
            for (int rr = 0; rr < RPT; rr++) {
                accA[rr] = ffma2(ux[rr][2*q],   ev.x, accA[rr]);
                accA[rr] = ffma2(ux[rr][2*q+1], ev.y, accA[rr]);
            }
        }
        #pragma unroll
        for (int q = 4; q < 8; q++) {            // dims 16..31
            ulonglong2 ev = se2[j*8 + q];
            #pragma unroll
            for (int rr = 0; rr < RPT; rr++) {
                accB[rr] = ffma2(ux[rr][2*q],   ev.x, accB[rr]);
                accB[rr] = ffma2(ux[rr][2*q+1], ev.y, accB[rr]);
            }
        }

        float cj = sc[j];
        #pragma unroll
        for (int rr = 0; rr < RPT; rr++) {
            unsigned long long r = addf2(accA[rr], accB[rr]);
            float dot = ulo(r) + uhi(r);
            float s = fmaf(-2.0f, dot, cj);
            if (s < best[rr])       { best2[rr] = best[rr]; best[rr] = s; bi[rr] = j; }
            else if (s < best2[rr]) { best2[rr] = s; }
        }
    }

    // epilogue
    float lsum = 0.0f;
    #pragma unroll
    for (int rr = 0; rr < RPT; rr++) {
        const int row = r0 + rr;
        bool contested = (best2[rr] - best[rr] < TAU);
        if (contested) {
            int slot = atomicAdd(&g_nwork, 1);
            if (slot < MAXWORK) { g_work[slot] = row; continue; }
        }
        const int j = bi[rr];
        out[OFF_IDX + row] = (float)j;
        atomicAdd(&g_counts[j], 1.0f);
        float* qout = out + OFF_QUANT + (size_t)row * DIM;
        #pragma unroll
        for (int p = 0; p < DIM / 2; p++) {
            float x0 = ulo(ux[rr][p]), x1 = uhi(ux[rr][p]);
            float q0 = se[j * DIM + 2*p], q1 = se[j * DIM + 2*p + 1];
            qout[2*p]   = q0;
            qout[2*p+1] = q1;
            float d0 = q0 - x0, d1 = q1 - x1;
            lsum = fmaf(d0, d0, lsum);
            lsum = fmaf(d1, d1, lsum);
            atomicAdd(&g_dw[j * DIM + 2*p],     x0);
            atomicAdd(&g_dw[j * DIM + 2*p + 1], x1);
        }
    }

    __shared__ float red[THREADS / 32];
    #pragma unroll
    for (int off = 16; off > 0; off >>= 1)
        lsum += __shfl_down_sync(0xFFFFFFFFu, lsum, off);
    if ((tid & 31) == 0) red[tid >> 5] = lsum;
    __syncthreads();
    if (tid == 0) {
        float s = 0.0f;
        #pragma unroll
        for (int w = 0; w < THREADS / 32; w++) s += red[w];
        atomicAdd(&g_loss, s);
    }
}

// ---------------------------------------------------------------------------
// k_refine: block-per-contested-row; exact ff rescan; lowest index within EPS.
// grid REFBLOCKS; blocks beyond worklist exit immediately.
// dynamic shared: codebook 128KB + norms hi/lo 8KB
// ---------------------------------------------------------------------------
__global__ void __launch_bounds__(256) k_refine(
    const float* __restrict__ flat,
    const float* __restrict__ emb,
    float* __restrict__ out)
{
    int nw = g_nwork; if (nw > MAXWORK) nw = MAXWORK;
    if ((int)blockIdx.x >= nw) return;

    extern __shared__ float rsm[];
    float* se  = rsm;                        // [KCODES*DIM]
    float* sch = rsm + KCODES * DIM;         // [KCODES]
    float* scl = sch + KCODES;               // [KCODES]
    __shared__ float x_s[DIM];
    __shared__ float rbh[256], rbl[256];
    __shared__ int   rpick[256];
    const int tid = threadIdx.x;

    {
        const float4* e4 = (const float4*)emb;
        float4* s4 = (float4*)se;
        for (int i = tid; i < KCODES * DIM / 4; i += 256) s4[i] = e4[i];
    }
    __syncthreads();
    for (int j = tid; j < KCODES; j += 256) {
        float dh = 0.0f, dl = 0.0f;
        #pragma unroll
        for (int k = 0; k < DIM; k++) {
            float v = se[j * DIM + k];
            float p = v * v;
            float pe = fmaf(v, v, -p);
            float s, err; two_sum(dh, p, s, err);
            dh = s; dl += (err + pe);
        }
        float h, l; two_sum(dh, dl, h, l);
        sch[j] = h; scl[j] = l;
    }
    __syncthreads();

    for (int w = blockIdx.x; w < nw; w += REFBLOCKS) {
        const int row = g_work[w];
        if (tid < DIM) x_s[tid] = flat[(size_t)row * DIM + tid];
        __syncthreads();

        // phase 1: exact ff best over all codes (each thread: 4 codes)
        float bh = 3.4e38f, bl = 0.0f;
        for (int j = tid; j < KCODES; j += 256) {
            float dh = 0.0f, dl = 0.0f;
            for (int k = 0; k < DIM; k++) {
                float xv = x_s[k];
                float ev = se[j * DIM + k];
                float p  = xv * ev;
                float pe = fmaf(xv, ev, -p);
                float s, err; two_sum(dh, p, s, err);
                dh = s; dl += (err + pe);
            }
            float h2 = -2.0f * dh, l2 = -2.0f * dl;
            float sh, serr; two_sum(sch[j], h2, sh, serr);
            float sl = serr + scl[j] + l2;
            float rh, rl; two_sum(sh, sl, rh, rl);
            if (rh < bh || (rh == bh && rl < bl)) { bh = rh; bl = rl; }
        }
        rbh[tid] = bh; rbl[tid] = bl;
        __syncthreads();
        for (int s = 128; s > 0; s >>= 1) {
            if (tid < s) {
                float oh = rbh[tid + s], ol = rbl[tid + s];
                if (oh < rbh[tid] || (oh == rbh[tid] && ol < rbl[tid])) {
                    rbh[tid] = oh; rbl[tid] = ol;
                }
            }
            __syncthreads();
        }
        bh = rbh[0]; bl = rbl[0];
        __syncthreads();

        // phase 2: lowest index within EPS of exact best
        int pick = KCODES;
        for (int j = tid; j < KCODES; j += 256) {
            float dh = 0.0f, dl = 0.0f;
            for (int k = 0; k < DIM; k++) {
                float xv = x_s[k];
                float ev = se[j * DIM + k];
                float p  = xv * ev;
                float pe = fmaf(xv, ev, -p);
                float s, err; two_sum(dh, p, s, err);
                dh = s; dl += (err + pe);
            }
            float h2 = -2.0f * dh, l2 = -2.0f * dl;
            float sh, serr; two_sum(sch[j], h2, sh, serr);
            float sl = serr + scl[j] + l2;
            float rh, rl; two_sum(sh, sl, rh, rl);
            float diff = (rh - bh) + (rl - bl);
            if (diff < EPS) { pick = j; break; }   // lowest j in this thread's strided set
        }
        rpick[tid] = pick;
        __syncthreads();
        for (int s = 128; s > 0; s >>= 1) {
            if (tid < s) rpick[tid] = min(rpick[tid], rpick[tid + s]);
            __syncthreads();
        }
        const int j = rpick[0];
        __syncthreads();

        // write results + stats (one warp: lane k = element k)
        if (tid < DIM) {
            float xk = x_s[tid];
            float qv = se[j * DIM + tid];
            out[OFF_QUANT + (size_t)row * DIM + tid] = qv;
            atomicAdd(&g_dw[j * DIM + tid], xk);
            float d = qv - xk;
            float l2s = d * d;
            #pragma unroll
            for (int off = 16; off > 0; off >>= 1)
                l2s += __shfl_down_sync(0xFFFFFFFFu, l2s, off);
            if (tid == 0) {
                out[OFF_IDX + row] = (float)j;
                atomicAdd(&g_counts[j], 1.0f);
                atomicAdd(&g_loss, l2s);
            }
        }
        __syncthreads();
    }
}

// ---------------------------------------------------------------------------
// k_fin1: small reductions only (1 block). ncs -> g_ncs + out; loss/perp.
// ---------------------------------------------------------------------------
__global__ void k_fin1(const float* __restrict__ cs_in,
                       float* __restrict__ out)
{
    __shared__ float sh[KCODES];
    __shared__ float n_sh;
    const int t = threadIdx.x;

    float cnt = g_counts[t];
    float pre = cs_in[t] * 0.99f + 0.01f * cnt;

    sh[t] = pre;
    __syncthreads();
    for (int s = KCODES / 2; s > 0; s >>= 1) {
        if (t < s) sh[t] += sh[t + s];
        __syncthreads();
    }
    if (t == 0) n_sh = sh[0];
    __syncthreads();
    const float n = n_sh;

    const float ncs = (pre + 1e-5f) / (n + (float)KCODES * 1e-5f) * n;
    g_ncs[t] = ncs;
    out[OFF_CS + t] = ncs;

    float p = cnt / (float)ROWS;
    float h = -p * logf(p + 1e-10f);
    __syncthreads();
    sh[t] = h;
    __syncthreads();
    for (int s = KCODES / 2; s > 0; s >>= 1) {
        if (t < s) sh[t] += sh[t + s];
        __syncthreads();
    }
    if (t == 0) {
        out[OFF_PERP] = expf(sh[0]);
        out[OFF_LOSS] = 0.25f * g_loss / (float)(ROWS * DIM);
    }
}

// ---------------------------------------------------------------------------
// k_fin2: full-chip EMA update (32768 threads, 1 element each)
// ---------------------------------------------------------------------------
__global__ void k_fin2(const float* __restrict__ ema_w,
                       float* __restrict__ out)
{
    int i = blockIdx.x * blockDim.x + threadIdx.x;   // 0..KCODES*DIM-1
    float w = ema_w[i] * 0.99f + 0.01f * g_dw[i];
    out[OFF_EMAW + i] = w;
    out[OFF_EMB  + i] = w / g_ncs[i >> 5];
}

// ---------------------------------------------------------------------------
extern "C" void kernel_launch(void* const* d_in, const int* in_sizes, int n_in,
                              void* d_out, int out_size)
{
    const float* inputs = (const float*)d_in[0];
    const float* emb    = (const float*)d_in[1];
    const float* cs     = (const float*)d_in[2];
    const float* emaw   = (const float*)d_in[3];
    float* out = (float*)d_out;

    size_t smem_main = (size_t)(KCODES * DIM + KCODES) * sizeof(float);          // 132 KB
    size_t smem_ref  = (size_t)(KCODES * DIM + 2 * KCODES) * sizeof(float);      // 136 KB
    cudaFuncSetAttribute(k_main,   cudaFuncAttributeMaxDynamicSharedMemorySize, (int)smem_main);
    cudaFuncSetAttribute(k_refine, cudaFuncAttributeMaxDynamicSharedMemorySize, (int)smem_ref);

    k_zero<<<(KCODES * DIM + 1023) / 1024, 1024>>>();
    k_main<<<NBLOCKS, THREADS, smem_main>>>(inputs, emb, out);
    k_refine<<<REFBLOCKS, 256, smem_ref>>>(inputs, emb, out);
    k_fin1<<<1, KCODES>>>(cs, out);
    k_fin2<<<KCODES * DIM / 512, 512>>>(emaw, out);
}

// round 10
// speedup vs baseline: 3.1617x; 1.1247x over previous
#include <cuda_runtime.h>
#include <math.h>

#define ROWS 131072
#define KCODES 1024
#define DIM 32
#define RPT 2
#define THREADS 512
#define NBLOCKS 148
#define TAU 5e-4f      // contested-row trigger (>> fp32 score noise)
#define EPS 5e-5f      // reference tie window (~6 ulps at magnitude ~64)
#define MAXWORK 4096
#define REFBLOCKS 64

// output layout (fp32 concatenation of the 7-tuple)
#define OFF_LOSS  0
#define OFF_QUANT 1
#define OFF_PERP  (OFF_QUANT + ROWS * DIM)
#define OFF_IDX   (OFF_PERP + 1)
#define OFF_EMB   (OFF_IDX + ROWS)
#define OFF_CS    (OFF_EMB + KCODES * DIM)
#define OFF_EMAW  (OFF_CS + KCODES)

__device__ float g_counts[KCODES];
__device__ float g_dw[KCODES * DIM];
__device__ float g_ncs[KCODES];
__device__ float g_loss;
__device__ int   g_nwork;
__device__ int   g_work[MAXWORK];

__global__ void k_zero() {
    int t = blockIdx.x * blockDim.x + threadIdx.x;
    if (t < KCODES * DIM) g_dw[t] = 0.0f;
    if (t < KCODES)       g_counts[t] = 0.0f;
    if (t == 0)         { g_loss = 0.0f; g_nwork = 0; }
}

// ---- packed fp32 helpers (Blackwell f32x2) --------------------------------
__device__ __forceinline__ unsigned long long ffma2(unsigned long long a,
                                                    unsigned long long b,
                                                    unsigned long long c) {
    unsigned long long d;
    asm("fma.rn.f32x2 %0, %1, %2, %3;" : "=l"(d) : "l"(a), "l"(b), "l"(c));
    return d;
}
__device__ __forceinline__ unsigned long long addf2(unsigned long long a,
                                                    unsigned long long b) {
    unsigned long long d;
    asm("add.rn.f32x2 %0, %1, %2;" : "=l"(d) : "l"(a), "l"(b));
    return d;
}
__device__ __forceinline__ float ulo(unsigned long long u) {
    return __uint_as_float((unsigned)u);
}
__device__ __forceinline__ float uhi(unsigned long long u) {
    return __uint_as_float((unsigned)(u >> 32));
}

__device__ __forceinline__ void two_sum(float a, float b, float &s, float &e) {
    s = a + b;
    float bb = s - a;
    e = (a - (s - bb)) + (b - bb);
}

// ---------------------------------------------------------------------------
// k_main: fp32 fast path with packed FFMA2. 148 blocks x 512 threads x 2 rows.
// Contested rows -> worklist. shared: codebook 128KB + ||e||^2 4KB
// NOTE: out+OFF_QUANT is only 4B-aligned (OFF_QUANT=1) -> quantized stores
// must be 32-bit scalars, never float4/float2.
// ---------------------------------------------------------------------------
extern __shared__ float smem[];

__global__ void __launch_bounds__(THREADS) k_main(
    const float* __restrict__ flat,
    const float* __restrict__ emb,
    float* __restrict__ out)
{
    float* se = smem;                 // [KCODES*DIM]
    float* sc = smem + KCODES * DIM;  // [KCODES]
    const int tid = threadIdx.x;

    {
        const float4* e4 = (const float4*)emb;
        float4* s4 = (float4*)se;
        #pragma unroll 4
        for (int i = tid; i < KCODES * DIM / 4; i += THREADS) s4[i] = e4[i];
    }
    __syncthreads();
    for (int j = tid; j < KCODES; j += THREADS) {
        float s = 0.0f;
        #pragma unroll
        for (int k = 0; k < DIM; k++) s = fmaf(se[j*DIM+k], se[j*DIM+k], s);
        sc[j] = s;
    }
    __syncthreads();

    const int g  = blockIdx.x * THREADS + tid;
    const int r0 = g * RPT;
    const bool active = (r0 < ROWS);

    // x rows as packed pairs: ux[rr][p] = (x[2p], x[2p+1])
    unsigned long long ux[RPT][DIM / 2];
    #pragma unroll
    for (int rr = 0; rr < RPT; rr++) {
        #pragma unroll
        for (int p = 0; p < DIM / 2; p++) ux[rr][p] = 0ull;
    }
    if (active) {
        #pragma unroll
        for (int rr = 0; rr < RPT; rr++) {
            const ulonglong2* xr = (const ulonglong2*)(flat + (size_t)(r0 + rr) * DIM);
            #pragma unroll
            for (int q = 0; q < DIM / 4; q++) {
                ulonglong2 v = xr[q];
                ux[rr][2*q]   = v.x;
                ux[rr][2*q+1] = v.y;
            }
        }
    }

    float best[RPT], best2[RPT];
    int   bi[RPT];
    #pragma unroll
    for (int rr = 0; rr < RPT; rr++) { best[rr] = 3.4e38f; best2[rr] = 3.4e38f; bi[rr] = 0; }

    const ulonglong2* se2 = (const ulonglong2*)se;
    if (active) {
        for (int j = 0; j < KCODES; j++) {
            unsigned long long accA[RPT], accB[RPT];
            #pragma unroll
            for (int rr = 0; rr < RPT; rr++) { accA[rr] = 0ull; accB[rr] = 0ull; }

            #pragma unroll
            for (int q = 0; q < 4; q++) {            // dims 0..15
                ulonglong2 ev = se2[j*8 + q];
                #pragma unroll
                for (int rr = 0; rr < RPT; rr++) {
                    accA[rr] = ffma2(ux[rr][2*q],   ev.x, accA[rr]);
                    accA[rr] = ffma2(ux[rr][2*q+1], ev.y, accA[rr]);
                }
            }
            #pragma unroll
            for (int q = 4; q < 8; q++) {            // dims 16..31
                ulonglong2 ev = se2[j*8 + q];
                #pragma unroll
                for (int rr = 0; rr < RPT; rr++) {
                    accB[rr] = ffma2(ux[rr][2*q],   ev.x, accB[rr]);
                    accB[rr] = ffma2(ux[rr][2*q+1], ev.y, accB[rr]);
                }
            }

            float cj = sc[j];
            #pragma unroll
            for (int rr = 0; rr < RPT; rr++) {
                unsigned long long r = addf2(accA[rr], accB[rr]);
                float dot = ulo(r) + uhi(r);
                float s = fmaf(-2.0f, dot, cj);
                // branchless second-best; strict < keeps first-min index
                best2[rr] = fminf(best2[rr], fmaxf(best[rr], s));
                if (s < best[rr]) { best[rr] = s; bi[rr] = j; }
            }
        }
    }

    // epilogue
    float lsum = 0.0f;
    if (active) {
        #pragma unroll
        for (int rr = 0; rr < RPT; rr++) {
            const int row = r0 + rr;
            bool contested = (best2[rr] - best[rr] < TAU);
            if (contested) {
                int slot = atomicAdd(&g_nwork, 1);
                if (slot < MAXWORK) { g_work[slot] = row; continue; }
            }
            const int j = bi[rr];
            out[OFF_IDX + row] = (float)j;
            atomicAdd(&g_counts[j], 1.0f);
            float* qout = out + OFF_QUANT + (size_t)row * DIM;  // 4B-aligned only!
            #pragma unroll
            for (int p = 0; p < DIM / 2; p++) {
                float x0 = ulo(ux[rr][p]), x1 = uhi(ux[rr][p]);
                float q0 = se[j * DIM + 2*p], q1 = se[j * DIM + 2*p + 1];
                qout[2*p]   = q0;                                // scalar STG.32
                qout[2*p+1] = q1;
                float d0 = q0 - x0, d1 = q1 - x1;
                lsum = fmaf(d0, d0, lsum);
                lsum = fmaf(d1, d1, lsum);
                atomicAdd(&g_dw[j * DIM + 2*p],     x0);
                atomicAdd(&g_dw[j * DIM + 2*p + 1], x1);
            }
        }
    }

    __shared__ float red[THREADS / 32];
    #pragma unroll
    for (int off = 16; off > 0; off >>= 1)
        lsum += __shfl_down_sync(0xFFFFFFFFu, lsum, off);
    if ((tid & 31) == 0) red[tid >> 5] = lsum;
    __syncthreads();
    if (tid == 0) {
        float s = 0.0f;
        #pragma unroll
        for (int w = 0; w < THREADS / 32; w++) s += red[w];
        atomicAdd(&g_loss, s);
    }
}

// ---------------------------------------------------------------------------
// k_refine: block-per-contested-row; exact ff rescan; lowest index within EPS.
// ---------------------------------------------------------------------------
__global__ void __launch_bounds__(256) k_refine(
    const float* __restrict__ flat,
    const float* __restrict__ emb,
    float* __restrict__ out)
{
    int nw = g_nwork; if (nw > MAXWORK) nw = MAXWORK;
    if ((int)blockIdx.x >= nw) return;

    extern __shared__ float rsm[];
    float* se  = rsm;                        // [KCODES*DIM]
    float* sch = rsm + KCODES * DIM;         // [KCODES]
    float* scl = sch + KCODES;               // [KCODES]
    __shared__ float x_s[DIM];
    __shared__ float rbh[256], rbl[256];
    __shared__ int   rpick[256];
    const int tid = threadIdx.x;

    {
        const float4* e4 = (const float4*)emb;
        float4* s4 = (float4*)se;
        for (int i = tid; i < KCODES * DIM / 4; i += 256) s4[i] = e4[i];
    }
    __syncthreads();
    for (int j = tid; j < KCODES; j += 256) {
        float dh = 0.0f, dl = 0.0f;
        #pragma unroll
        for (int k = 0; k < DIM; k++) {
            float v = se[j * DIM + k];
            float p = v * v;
            float pe = fmaf(v, v, -p);
            float s, err; two_sum(dh, p, s, err);
            dh = s; dl += (err + pe);
        }
        float h, l; two_sum(dh, dl, h, l);
        sch[j] = h; scl[j] = l;
    }
    __syncthreads();

    for (int w = blockIdx.x; w < nw; w += REFBLOCKS) {
        const int row = g_work[w];
        if (tid < DIM) x_s[tid] = flat[(size_t)row * DIM + tid];
        __syncthreads();

        // phase 1: exact ff best over all codes
        float bh = 3.4e38f, bl = 0.0f;
        for (int j = tid; j < KCODES; j += 256) {
            float dh = 0.0f, dl = 0.0f;
            for (int k = 0; k < DIM; k++) {
                float xv = x_s[k];
                float ev = se[j * DIM + k];
                float p  = xv * ev;
                float pe = fmaf(xv, ev, -p);
                float s, err; two_sum(dh, p, s, err);
                dh = s; dl += (err + pe);
            }
            float h2 = -2.0f * dh, l2 = -2.0f * dl;
            float sh, serr; two_sum(sch[j], h2, sh, serr);
            float sl = serr + scl[j] + l2;
            float rh, rl; two_sum(sh, sl, rh, rl);
            if (rh < bh || (rh == bh && rl < bl)) { bh = rh; bl = rl; }
        }
        rbh[tid] = bh; rbl[tid] = bl;
        __syncthreads();
        for (int s = 128; s > 0; s >>= 1) {
            if (tid < s) {
                float oh = rbh[tid + s], ol = rbl[tid + s];
                if (oh < rbh[tid] || (oh == rbh[tid] && ol < rbl[tid])) {
                    rbh[tid] = oh; rbl[tid] = ol;
                }
            }
            __syncthreads();
        }
        bh = rbh[0]; bl = rbl[0];
        __syncthreads();

        // phase 2: lowest index within EPS of exact best
        int pick = KCODES;
        for (int j = tid; j < KCODES; j += 256) {
            float dh = 0.0f, dl = 0.0f;
            for (int k = 0; k < DIM; k++) {
                float xv = x_s[k];
                float ev = se[j * DIM + k];
                float p  = xv * ev;
                float pe = fmaf(xv, ev, -p);
                float s, err; two_sum(dh, p, s, err);
                dh = s; dl += (err + pe);
            }
            float h2 = -2.0f * dh, l2 = -2.0f * dl;
            float sh, serr; two_sum(sch[j], h2, sh, serr);
            float sl = serr + scl[j] + l2;
            float rh, rl; two_sum(sh, sl, rh, rl);
            float diff = (rh - bh) + (rl - bl);
            if (diff < EPS) { pick = j; break; }
        }
        rpick[tid] = pick;
        __syncthreads();
        for (int s = 128; s > 0; s >>= 1) {
            if (tid < s) rpick[tid] = min(rpick[tid], rpick[tid + s]);
            __syncthreads();
        }
        const int j = rpick[0];
        __syncthreads();

        if (tid < DIM) {
            float xk = x_s[tid];
            float qv = se[j * DIM + tid];
            out[OFF_QUANT + (size_t)row * DIM + tid] = qv;
            atomicAdd(&g_dw[j * DIM + tid], xk);
            float d = qv - xk;
            float l2s = d * d;
            #pragma unroll
            for (int off = 16; off > 0; off >>= 1)
                l2s += __shfl_down_sync(0xFFFFFFFFu, l2s, off);
            if (tid == 0) {
                out[OFF_IDX + row] = (float)j;
                atomicAdd(&g_counts[j], 1.0f);
                atomicAdd(&g_loss, l2s);
            }
        }
        __syncthreads();
    }
}

// ---------------------------------------------------------------------------
__global__ void k_fin1(const float* __restrict__ cs_in,
                       float* __restrict__ out)
{
    __shared__ float sh[KCODES];
    __shared__ float n_sh;
    const int t = threadIdx.x;

    float cnt = g_counts[t];
    float pre = cs_in[t] * 0.99f + 0.01f * cnt;

    sh[t] = pre;
    __syncthreads();
    for (int s = KCODES / 2; s > 0; s >>= 1) {
        if (t < s) sh[t] += sh[t + s];
        __syncthreads();
    }
    if (t == 0) n_sh = sh[0];
    __syncthreads();
    const float n = n_sh;

    const float ncs = (pre + 1e-5f) / (n + (float)KCODES * 1e-5f) * n;
    g_ncs[t] = ncs;
    out[OFF_CS + t] = ncs;

    float p = cnt / (float)ROWS;
    float h = -p * logf(p + 1e-10f);
    __syncthreads();
    sh[t] = h;
    __syncthreads();
    for (int s = KCODES / 2; s > 0; s >>= 1) {
        if (t < s) sh[t] += sh[t + s];
        __syncthreads();
    }
    if (t == 0) {
        out[OFF_PERP] = expf(sh[0]);
        out[OFF_LOSS] = 0.25f * g_loss / (float)(ROWS * DIM);
    }
}

__global__ void k_fin2(const float* __restrict__ ema_w,
                       float* __restrict__ out)
{
    int i = blockIdx.x * blockDim.x + threadIdx.x;   // 0..KCODES*DIM-1
    float w = ema_w[i] * 0.99f + 0.01f * g_dw[i];
    out[OFF_EMAW + i] = w;
    out[OFF_EMB  + i] = w / g_ncs[i >> 5];
}

// ---------------------------------------------------------------------------
extern "C" void kernel_launch(void* const* d_in, const int* in_sizes, int n_in,
                              void* d_out, int out_size)
{
    const float* inputs = (const float*)d_in[0];
    const float* emb    = (const float*)d_in[1];
    const float* cs     = (const float*)d_in[2];
    const float* emaw   = (const float*)d_in[3];
    float* out = (float*)d_out;

    size_t smem_main = (size_t)(KCODES * DIM + KCODES) * sizeof(float);          // 132 KB
    size_t smem_ref  = (size_t)(KCODES * DIM + 2 * KCODES) * sizeof(float);      // 136 KB
    cudaFuncSetAttribute(k_main,   cudaFuncAttributeMaxDynamicSharedMemorySize, (int)smem_main);
    cudaFuncSetAttribute(k_refine, cudaFuncAttributeMaxDynamicSharedMemorySize, (int)smem_ref);

    k_zero<<<(KCODES * DIM + 1023) / 1024, 1024>>>();
    k_main<<<NBLOCKS, THREADS, smem_main>>>(inputs, emb, out);
    k_refine<<<REFBLOCKS, 256, smem_ref>>>(inputs, emb, out);
    k_fin1<<<1, KCODES>>>(cs, out);
    k_fin2<<<KCODES * DIM / 512, 512>>>(emaw, out);
}